// round 16
// baseline (speedup 1.0000x reference)
#include <cuda_runtime.h>
#include <cstdint>

#define NV_MAX 50000
#define HDIM 64

// -------- scratch (no allocs allowed) --------
__device__ float g_A[NV_MAX * HDIM];
__device__ float g_B[NV_MAX * HDIM];
__device__ float g_P[NV_MAX * HDIM];
__device__ float g_Q[NV_MAX * HDIM];
__device__ float g_aggr[NV_MAX * HDIM];
__device__ float g_aggrp[NV_MAX * HDIM];
// precomputed tf32 W fragments (hi[4096] ++ lo[4096] per 64x64 set)
__device__ float g_fragM[8192];            // msg_w2
__device__ float g_fragP[8192];            // mpos_w2
__device__ float g_fragUpd[4 * 8192];      // upd_w1 ch0..2, upd_w2
__device__ float g_fragUpe[3 * 8192];      // upe_w1 ch0..1, upe_w2
__device__ float g_fragPreM[4 * 8192];     // msg_w1 blocks (nh,kc)
__device__ float g_fragPreP[2 * 8192];     // mpos_w1 blocks nh=0,1

typedef unsigned long long ull_t;

__device__ __forceinline__ float tanh_f(float x) {
    float y; asm("tanh.approx.f32 %0, %1;" : "=f"(y) : "f"(x)); return y;
}
__device__ __forceinline__ float silu_f(float x) {
    return 0.5f * x * (1.0f + tanh_f(0.5f * x));   // single MUFU
}
__device__ __forceinline__ uint32_t f2tf32(float x) {
    uint32_t r; asm("cvt.rna.tf32.f32 %0, %1;" : "=r"(r) : "f"(x)); return r;
}
__device__ __forceinline__ void mma_tf32(float c[4],
    uint32_t a0, uint32_t a1, uint32_t a2, uint32_t a3, uint32_t b0, uint32_t b1)
{
    asm volatile(
        "mma.sync.aligned.m16n8k8.row.col.f32.tf32.tf32.f32 "
        "{%0,%1,%2,%3}, {%4,%5,%6,%7}, {%8,%9}, {%0,%1,%2,%3};"
        : "+f"(c[0]), "+f"(c[1]), "+f"(c[2]), "+f"(c[3])
        : "r"(a0), "r"(a1), "r"(a2), "r"(a3), "r"(b0), "r"(b1));
}

// coalesced copy of one 8192-float frag set (hi+lo) into smem
__device__ __forceinline__ void copy_frag(const float* __restrict__ src,
                                          float* __restrict__ dst, int tid)
{
    const float4* s4 = (const float4*)src;
    float4* d4 = (float4*)dst;
    #pragma unroll
    for (int i = 0; i < 8; i++) d4[tid + 256 * i] = s4[tid + 256 * i];
}

// ============================================================
// Kernel 0: W-fragment precompute, one CTA per 64x64 set (15 CTAs)
// ============================================================
__device__ __forceinline__ void build_one(
    const float* __restrict__ src, float* __restrict__ dst, int tid)
{
    for (int idx = tid; idx < 2048; idx += 256) {
        int kt = idx >> 8;
        int nt = (idx >> 5) & 7;
        int ln = idx & 31;
        int g = ln >> 2, t = ln & 3;
        int r = 8 * kt + t, c = 8 * nt + g;
        float w0 = src[r * 64 + c];
        float w1 = src[(r + 4) * 64 + c];
        uint32_t h0 = f2tf32(w0), h1 = f2tf32(w1);
        dst[2 * idx]            = __uint_as_float(h0);
        dst[2 * idx + 1]        = __uint_as_float(h1);
        dst[4096 + 2 * idx]     = __uint_as_float(f2tf32(w0 - __uint_as_float(h0)));
        dst[4096 + 2 * idx + 1] = __uint_as_float(f2tf32(w1 - __uint_as_float(h1)));
    }
}

__global__ void wfrag_kernel(
    const float* __restrict__ msg_w1,  const float* __restrict__ msg_w2,
    const float* __restrict__ mpos_w1, const float* __restrict__ mpos_w2,
    const float* __restrict__ upd_w1,  const float* __restrict__ upd_w2,
    const float* __restrict__ upe_w1,  const float* __restrict__ upe_w2)
{
    int tid = threadIdx.x;
    int b = blockIdx.x;
    if (b == 0)       build_one(msg_w2,  g_fragM, tid);
    else if (b == 1)  build_one(mpos_w2, g_fragP, tid);
    else if (b <= 4)  build_one(upd_w1 + (b - 2) * 4096, g_fragUpd + (b - 2) * 8192, tid);
    else if (b == 5)  build_one(upd_w2, g_fragUpd + 3 * 8192, tid);
    else if (b <= 7)  build_one(upe_w1 + (b - 6) * 4096, g_fragUpe + (b - 6) * 8192, tid);
    else if (b == 8)  build_one(upe_w2, g_fragUpe + 2 * 8192, tid);
    else if (b <= 12) {
        int s = b - 9;                 // s = nh*2 + kc
        int nh = s >> 1, kc = s & 1;
        build_one(msg_w1 + (nh * 128 + kc * 64) * 64, g_fragPreM + s * 8192, tid);
    } else {
        int nh = b - 13;
        build_one(mpos_w1 + nh * 64 * 64, g_fragPreP + nh * 8192, tid);
    }
}

// ============================================================
// Kernel 1 (fused, tf32 mma): blockIdx.y==0 -> A,B (+zero aggr); ==1 -> P,Q
// (unchanged R15 champion)
// ============================================================
__global__ void __launch_bounds__(256, 3) pre_kernel(
    const float* __restrict__ x, const float* __restrict__ pe,
    const float* __restrict__ msg_b1, const float* __restrict__ mpos_b1,
    int N)
{
    extern __shared__ float sm[];
    float* sh_inT = sm;                    // [64][132]
    float* sh_Whi = sh_inT + 64 * 132;     // 4096
    float* sh_Wlo = sh_Whi + 4096;         // 4096
    float* sh_b   = sh_Wlo + 4096;         // [128]

    bool is_pos = (blockIdx.y != 0);
    const float* fragbase = is_pos ? g_fragPreP : g_fragPreM;
    int nkc = is_pos ? 1 : 2;

    int tid = threadIdx.x;
    int nb = blockIdx.x * 128;
    if (tid < 128) sh_b[tid] = (tid < 64) ? (is_pos ? mpos_b1[tid] : msg_b1[tid]) : 0.0f;

    if (!is_pos) {
        for (int idx = tid; idx < 4096; idx += 256) {
            int n = idx & 127, s = (idx >> 7) & 15, which = idx >> 11;
            int gn = nb + n;
            if (gn < N) {
                float4* dst = (float4*)((which ? g_aggrp : g_aggr) + (size_t)gn * 64) + s;
                *dst = make_float4(0.f, 0.f, 0.f, 0.f);
            }
        }
    }

    int w = tid >> 5, lane = tid & 31;
    int gid = lane >> 2, tig = lane & 3;
    int m0 = w * 16;

    #pragma unroll 1
    for (int nh = 0; nh < 2; nh++) {
        float acc[8][4];
        #pragma unroll
        for (int nt = 0; nt < 8; nt++) {
            acc[nt][0] = 0.f; acc[nt][1] = 0.f; acc[nt][2] = 0.f; acc[nt][3] = 0.f;
        }

        #pragma unroll 1
        for (int kc = 0; kc < nkc; kc++) {
            __syncthreads();
            copy_frag(fragbase + (nh * nkc + kc) * 8192, sh_Whi, tid);
            const float* src = is_pos ? pe : ((kc == 0) ? x : pe);
            for (int idx = tid; idx < 16 * 128; idx += 256) {
                int n = idx & 127, k4 = idx >> 7;
                int gn = nb + n;
                float4 v = make_float4(0.f, 0.f, 0.f, 0.f);
                if (gn < N) v = *(const float4*)(src + (size_t)gn * 64 + 4 * k4);
                sh_inT[(4 * k4 + 0) * 132 + n] = v.x;
                sh_inT[(4 * k4 + 1) * 132 + n] = v.y;
                sh_inT[(4 * k4 + 2) * 132 + n] = v.z;
                sh_inT[(4 * k4 + 3) * 132 + n] = v.w;
            }
            __syncthreads();
            #pragma unroll 2
            for (int kt = 0; kt < 8; kt++) {
                const float* tk = sh_inT + (8 * kt + tig) * 132 + m0 + gid;
                float a0f = tk[0],       a1f = tk[8];
                float a2f = tk[4 * 132], a3f = tk[4 * 132 + 8];
                uint32_t ah0 = f2tf32(a0f), ah1 = f2tf32(a1f);
                uint32_t ah2 = f2tf32(a2f), ah3 = f2tf32(a3f);
                uint32_t al0 = f2tf32(a0f - __uint_as_float(ah0));
                uint32_t al1 = f2tf32(a1f - __uint_as_float(ah1));
                uint32_t al2 = f2tf32(a2f - __uint_as_float(ah2));
                uint32_t al3 = f2tf32(a3f - __uint_as_float(ah3));
                #pragma unroll
                for (int nt = 0; nt < 8; nt++) {
                    int fo = ((kt * 8 + nt) * 32 + lane) * 2;
                    float2 bh = *(const float2*)(sh_Whi + fo);
                    float2 bl = *(const float2*)(sh_Wlo + fo);
                    uint32_t bh0 = __float_as_uint(bh.x), bh1 = __float_as_uint(bh.y);
                    uint32_t bl0 = __float_as_uint(bl.x), bl1 = __float_as_uint(bl.y);
                    mma_tf32(acc[nt], ah0, ah1, ah2, ah3, bh0, bh1);
                    mma_tf32(acc[nt], ah0, ah1, ah2, ah3, bl0, bl1);
                    mma_tf32(acc[nt], al0, al1, al2, al3, bh0, bh1);
                }
            }
        }

        float* dst = is_pos ? (nh ? g_Q : g_P) : (nh ? g_B : g_A);
        const float* bb = sh_b + nh * 64;
        int g0 = nb + m0 + gid, g1 = g0 + 8;
        #pragma unroll
        for (int nt = 0; nt < 8; nt++) {
            int c = 8 * nt + 2 * tig;
            float b0 = bb[c], b1 = bb[c + 1];
            if (g0 < N)
                *(float2*)(dst + (size_t)g0 * 64 + c) =
                    make_float2(acc[nt][0] + b0, acc[nt][1] + b1);
            if (g1 < N)
                *(float2*)(dst + (size_t)g1 * 64 + c) =
                    make_float2(acc[nt][2] + b0, acc[nt][3] + b1);
        }
    }
}

// ============================================================
// Kernel 2: edge kernel — tf32 mma, 2xTF32 (ah·bh + ah·bl; al term dropped)
// ============================================================
template <bool IS_TANH>
__device__ __forceinline__ void edge_mma_path(
    const float* __restrict__ sh_t, const float* __restrict__ sh_Whi,
    const float* __restrict__ sh_Wlo, const float* __restrict__ bias,
    const int* __restrict__ rec, float* __restrict__ aggr,
    int w, int lane, int eb, int E)
{
    int gid = lane >> 2, tig = lane & 3;
    int e0 = w * 16;

    float acc[8][4];
    #pragma unroll
    for (int nt = 0; nt < 8; nt++) {
        acc[nt][0] = 0.f; acc[nt][1] = 0.f; acc[nt][2] = 0.f; acc[nt][3] = 0.f;
    }

    #pragma unroll 2
    for (int kt = 0; kt < 8; kt++) {
        const float* tk = sh_t + (8 * kt + tig) * 132 + e0 + gid;
        uint32_t a0h = f2tf32(tk[0]);
        uint32_t a1h = f2tf32(tk[8]);
        uint32_t a2h = f2tf32(tk[4 * 132]);
        uint32_t a3h = f2tf32(tk[4 * 132 + 8]);
        #pragma unroll
        for (int nt = 0; nt < 8; nt++) {
            int fo = ((kt * 8 + nt) * 32 + lane) * 2;
            float2 bh = *(const float2*)(sh_Whi + fo);
            float2 bl = *(const float2*)(sh_Wlo + fo);
            uint32_t bh0 = __float_as_uint(bh.x), bh1 = __float_as_uint(bh.y);
            uint32_t bl0 = __float_as_uint(bl.x), bl1 = __float_as_uint(bl.y);
            mma_tf32(acc[nt], a0h, a1h, a2h, a3h, bh0, bh1);
            mma_tf32(acc[nt], a0h, a1h, a2h, a3h, bl0, bl1);
        }
    }

    int el0 = e0 + gid, el1 = el0 + 8;
    bool v0 = (eb + el0 < E), v1 = (eb + el1 < E);
    int rc0 = rec[el0], rc1 = rec[el1];
    #pragma unroll
    for (int nt = 0; nt < 8; nt++) {
        int c = 8 * nt + 2 * tig;
        float b0 = bias[c], b1 = bias[c + 1];
        if (v0) {
            float m0 = acc[nt][0] + b0, m1 = acc[nt][1] + b1;
            if (IS_TANH) { m0 = tanh_f(m0); m1 = tanh_f(m1); }
            else         { m0 = silu_f(m0); m1 = silu_f(m1); }
            float* dst = aggr + (size_t)rc0 * 64 + c;
            asm volatile("red.global.add.v2.f32 [%0], {%1,%2};"
                         :: "l"(dst), "f"(m0), "f"(m1) : "memory");
        }
        if (v1) {
            float m0 = acc[nt][2] + b0, m1 = acc[nt][3] + b1;
            if (IS_TANH) { m0 = tanh_f(m0); m1 = tanh_f(m1); }
            else         { m0 = silu_f(m0); m1 = silu_f(m1); }
            float* dst = aggr + (size_t)rc1 * 64 + c;
            asm volatile("red.global.add.v2.f32 [%0], {%1,%2};"
                         :: "l"(dst), "f"(m0), "f"(m1) : "memory");
        }
    }
}

__global__ void __launch_bounds__(256, 3) edge_kernel(
    const float* __restrict__ pos,
    const int* __restrict__ ei,          // int32 (JAX demotes int64)
    const float* __restrict__ msg_w1,
    const float* __restrict__ msg_b2,
    const float* __restrict__ mpos_w1,
    const float* __restrict__ mpos_b2,
    int E)
{
    extern __shared__ float sm[];
    float* sh_t   = sm;                    // [64][132]
    float* sh_Whi = sh_t + 64 * 132;       // 4096 (hi; lo contiguous)
    float* sh_Wlo = sh_Whi + 4096;         // 4096
    float* sh_we  = sh_Wlo + 4096;         // [64]
    float* sh_ve  = sh_we + 64;
    float* sh_bm  = sh_ve + 64;
    float* sh_bp  = sh_bm + 64;
    int*   sh_rec = (int*)(sh_bp + 64);    // [128]

    int tid = threadIdx.x;
    copy_frag(g_fragM, sh_Whi, tid);
    if (tid < 64) {
        sh_we[tid] = msg_w1[256 * 64 + tid];
        sh_ve[tid] = mpos_w1[128 * 64 + tid];
        sh_bm[tid] = msg_b2[tid];
        sh_bp[tid] = mpos_b2[tid];
    }

    int eb = blockIdx.x * 128;
    int e  = tid & 127;
    int half = tid >> 7;
    int eg = eb + e;
    bool valid = eg < E;
    int snd = 0, rcv = 0;
    if (valid) { snd = ei[eg]; rcv = ei[E + eg]; }
    if (half == 0) sh_rec[e] = rcv;
    float dist = 0.0f;
    if (valid) {
        float dx = pos[snd * 3 + 0] - pos[rcv * 3 + 0];
        float dy = pos[snd * 3 + 1] - pos[rcv * 3 + 1];
        float dz = pos[snd * 3 + 2] - pos[rcv * 3 + 2];
        dist = sqrtf(dx * dx + dy * dy + dz * dz);
    }
    __syncthreads();

    int c0h = half * 32;
    int w = tid >> 5, lane = tid & 31;

    // ---- phase A: silu(A[snd]+B[rcv]+dist*we) -> sh_t, then msg GEMM ----
    {
        const float4* A4 = (const float4*)(g_A + (size_t)snd * 64 + c0h);
        const float4* B4 = (const float4*)(g_B + (size_t)rcv * 64 + c0h);
        const float4* W4 = (const float4*)(sh_we + c0h);
        #pragma unroll
        for (int j = 0; j < 8; j++) {
            float4 a = A4[j], b = B4[j], wv = W4[j];
            float* dst = sh_t + (c0h + 4 * j) * 132 + e;
            dst[0]   = silu_f(a.x + b.x + dist * wv.x);
            dst[132] = silu_f(a.y + b.y + dist * wv.y);
            dst[264] = silu_f(a.z + b.z + dist * wv.z);
            dst[396] = silu_f(a.w + b.w + dist * wv.w);
        }
    }
    __syncthreads();
    edge_mma_path<false>(sh_t, sh_Whi, sh_Wlo, sh_bm, sh_rec, g_aggr, w, lane, eb, E);
    __syncthreads();

    // ---- phase B: copy pos frags; tanh tile; pos GEMM ----
    copy_frag(g_fragP, sh_Whi, tid);
    {
        const float4* P4 = (const float4*)(g_P + (size_t)snd * 64 + c0h);
        const float4* Q4 = (const float4*)(g_Q + (size_t)rcv * 64 + c0h);
        const float4* V4 = (const float4*)(sh_ve + c0h);
        #pragma unroll
        for (int j = 0; j < 8; j++) {
            float4 p = P4[j], q = Q4[j], v = V4[j];
            float* dst = sh_t + (c0h + 4 * j) * 132 + e;
            dst[0]   = tanh_f(p.x + q.x + dist * v.x);
            dst[132] = tanh_f(p.y + q.y + dist * v.y);
            dst[264] = tanh_f(p.z + q.z + dist * v.z);
            dst[396] = tanh_f(p.w + q.w + dist * v.w);
        }
    }
    __syncthreads();
    edge_mma_path<true>(sh_t, sh_Whi, sh_Wlo, sh_bp, sh_rec, g_aggrp, w, lane, eb, E);
}

// ============================================================
// Kernel 3 (fused): tf32 mma with precomputed frags
// (unchanged R14/R15 champion)
// ============================================================
__global__ void __launch_bounds__(256, 3) upd_kernel(
    const float* __restrict__ x, const float* __restrict__ pe,
    const float* __restrict__ upd_b1, const float* __restrict__ upd_b2,
    const float* __restrict__ upe_b1, const float* __restrict__ upe_b2,
    float* __restrict__ out, int N)
{
    extern __shared__ float sm[];
    float* sh_inT = sm;                    // [64][132] (chunk; reused as hT)
    float* sh_Whi = sh_inT + 64 * 132;     // 4096
    float* sh_Wlo = sh_Whi + 4096;         // 4096
    float* sh_b1  = sh_Wlo + 4096;         // [64]
    float* sh_b2  = sh_b1 + 64;            // [64]

    bool is_pe = (blockIdx.y != 0);
    const float* fragbase = is_pe ? g_fragUpe : g_fragUpd;
    int nchunks = is_pe ? 2 : 3;

    int tid = threadIdx.x;
    int nb = blockIdx.x * 128;
    if (tid < 64) {
        sh_b1[tid] = is_pe ? upe_b1[tid] : upd_b1[tid];
        sh_b2[tid] = is_pe ? upe_b2[tid] : upd_b2[tid];
    }

    int w = tid >> 5, lane = tid & 31;
    int gid = lane >> 2, tig = lane & 3;
    int m0 = w * 16;

    float acc[8][4];
    #pragma unroll
    for (int nt = 0; nt < 8; nt++) {
        acc[nt][0] = 0.f; acc[nt][1] = 0.f; acc[nt][2] = 0.f; acc[nt][3] = 0.f;
    }

    #pragma unroll 1
    for (int ch = 0; ch < nchunks; ch++) {
        __syncthreads();
        copy_frag(fragbase + ch * 8192, sh_Whi, tid);
        const float* src = is_pe ? ((ch == 0) ? pe : g_aggrp)
                                 : ((ch == 0) ? x : (ch == 1) ? pe : g_aggr);
        for (int idx = tid; idx < 16 * 128; idx += 256) {
            int n = idx & 127, k4 = idx >> 7;
            int gn = nb + n;
            float4 v = make_float4(0.f, 0.f, 0.f, 0.f);
            if (gn < N) v = *(const float4*)(src + (size_t)gn * 64 + 4 * k4);
            sh_inT[(4 * k4 + 0) * 132 + n] = v.x;
            sh_inT[(4 * k4 + 1) * 132 + n] = v.y;
            sh_inT[(4 * k4 + 2) * 132 + n] = v.z;
            sh_inT[(4 * k4 + 3) * 132 + n] = v.w;
        }
        __syncthreads();
        #pragma unroll 2
        for (int kt = 0; kt < 8; kt++) {
            const float* tk = sh_inT + (8 * kt + tig) * 132 + m0 + gid;
            float a0f = tk[0],       a1f = tk[8];
            float a2f = tk[4 * 132], a3f = tk[4 * 132 + 8];
            uint32_t ah0 = f2tf32(a0f), ah1 = f2tf32(a1f);
            uint32_t ah2 = f2tf32(a2f), ah3 = f2tf32(a3f);
            uint32_t al0 = f2tf32(a0f - __uint_as_float(ah0));
            uint32_t al1 = f2tf32(a1f - __uint_as_float(ah1));
            uint32_t al2 = f2tf32(a2f - __uint_as_float(ah2));
            uint32_t al3 = f2tf32(a3f - __uint_as_float(ah3));
            #pragma unroll
            for (int nt = 0; nt < 8; nt++) {
                int fo = ((kt * 8 + nt) * 32 + lane) * 2;
                float2 bh = *(const float2*)(sh_Whi + fo);
                float2 bl = *(const float2*)(sh_Wlo + fo);
                uint32_t bh0 = __float_as_uint(bh.x), bh1 = __float_as_uint(bh.y);
                uint32_t bl0 = __float_as_uint(bl.x), bl1 = __float_as_uint(bl.y);
                mma_tf32(acc[nt], ah0, ah1, ah2, ah3, bh0, bh1);
                mma_tf32(acc[nt], ah0, ah1, ah2, ah3, bl0, bl1);
                mma_tf32(acc[nt], al0, al1, al2, al3, bh0, bh1);
            }
        }
    }

    __syncthreads();
    #pragma unroll
    for (int nt = 0; nt < 8; nt++) {
        int c = 8 * nt + 2 * tig;
        float b0 = sh_b1[c], b1 = sh_b1[c + 1];
        float h00 = acc[nt][0] + b0, h01 = acc[nt][1] + b1;
        float h10 = acc[nt][2] + b0, h11 = acc[nt][3] + b1;
        if (is_pe) { h00 = tanh_f(h00); h01 = tanh_f(h01); h10 = tanh_f(h10); h11 = tanh_f(h11); }
        else       { h00 = silu_f(h00); h01 = silu_f(h01); h10 = silu_f(h10); h11 = silu_f(h11); }
        sh_inT[c * 132 + m0 + gid]           = h00;
        sh_inT[(c + 1) * 132 + m0 + gid]     = h01;
        sh_inT[c * 132 + m0 + gid + 8]       = h10;
        sh_inT[(c + 1) * 132 + m0 + gid + 8] = h11;
    }
    copy_frag(fragbase + (is_pe ? 2 : 3) * 8192, sh_Whi, tid);
    __syncthreads();

    float a2[8][4];
    #pragma unroll
    for (int nt = 0; nt < 8; nt++) {
        a2[nt][0] = 0.f; a2[nt][1] = 0.f; a2[nt][2] = 0.f; a2[nt][3] = 0.f;
    }
    #pragma unroll 2
    for (int kt = 0; kt < 8; kt++) {
        const float* tk = sh_inT + (8 * kt + tig) * 132 + m0 + gid;
        float a0f = tk[0],       a1f = tk[8];
        float a2f = tk[4 * 132], a3f = tk[4 * 132 + 8];
        uint32_t ah0 = f2tf32(a0f), ah1 = f2tf32(a1f);
        uint32_t ah2 = f2tf32(a2f), ah3 = f2tf32(a3f);
        uint32_t al0 = f2tf32(a0f - __uint_as_float(ah0));
        uint32_t al1 = f2tf32(a1f - __uint_as_float(ah1));
        uint32_t al2 = f2tf32(a2f - __uint_as_float(ah2));
        uint32_t al3 = f2tf32(a3f - __uint_as_float(ah3));
        #pragma unroll
        for (int nt = 0; nt < 8; nt++) {
            int fo = ((kt * 8 + nt) * 32 + lane) * 2;
            float2 bh = *(const float2*)(sh_Whi + fo);
            float2 bl = *(const float2*)(sh_Wlo + fo);
            uint32_t bh0 = __float_as_uint(bh.x), bh1 = __float_as_uint(bh.y);
            uint32_t bl0 = __float_as_uint(bl.x), bl1 = __float_as_uint(bl.y);
            mma_tf32(a2[nt], ah0, ah1, ah2, ah3, bh0, bh1);
            mma_tf32(a2[nt], ah0, ah1, ah2, ah3, bl0, bl1);
            mma_tf32(a2[nt], al0, al1, al2, al3, bh0, bh1);
        }
    }

    float* obase = out + (is_pe ? (size_t)N * 64 : 0);
    int g0 = nb + m0 + gid, g1 = g0 + 8;
    #pragma unroll
    for (int nt = 0; nt < 8; nt++) {
        int c = 8 * nt + 2 * tig;
        float b0 = sh_b2[c], b1 = sh_b2[c + 1];
        if (g0 < N) {
            float o0 = a2[nt][0] + b0, o1 = a2[nt][1] + b1;
            if (is_pe) { o0 = tanh_f(o0); o1 = tanh_f(o1); }
            *(float2*)(obase + (size_t)g0 * 64 + c) = make_float2(o0, o1);
        }
        if (g1 < N) {
            float o0 = a2[nt][2] + b0, o1 = a2[nt][3] + b1;
            if (is_pe) { o0 = tanh_f(o0); o1 = tanh_f(o1); }
            *(float2*)(obase + (size_t)g1 * 64 + c) = make_float2(o0, o1);
        }
    }
}

// ============================================================
// Host launch
// ============================================================
extern "C" void kernel_launch(void* const* d_in, const int* in_sizes, int n_in,
                              void* d_out, int out_size)
{
    const float* x       = (const float*)d_in[0];
    const float* pos     = (const float*)d_in[1];
    const float* pe      = (const float*)d_in[2];
    const int*   ei      = (const int*)d_in[3];
    const float* msg_w1  = (const float*)d_in[4];
    const float* msg_b1  = (const float*)d_in[5];
    const float* msg_w2  = (const float*)d_in[6];
    const float* msg_b2  = (const float*)d_in[7];
    const float* mpos_w1 = (const float*)d_in[8];
    const float* mpos_b1 = (const float*)d_in[9];
    const float* mpos_w2 = (const float*)d_in[10];
    const float* mpos_b2 = (const float*)d_in[11];
    const float* upd_w1  = (const float*)d_in[12];
    const float* upd_b1  = (const float*)d_in[13];
    const float* upd_w2  = (const float*)d_in[14];
    const float* upd_b2  = (const float*)d_in[15];
    const float* upe_w1  = (const float*)d_in[16];
    const float* upe_b1  = (const float*)d_in[17];
    const float* upe_w2  = (const float*)d_in[18];
    const float* upe_b2  = (const float*)d_in[19];

    int N = in_sizes[0] / 64;
    int E = in_sizes[3] / 2;

    const int SMEM_PRE  = (64 * 132 + 4096 + 4096 + 128) * 4;              // 67,072 B
    const int SMEM_EDGE = (64 * 132 + 4096 + 4096 + 256) * 4 + 512;        // 68,096 B
    const int SMEM_UPD  = (64 * 132 + 4096 + 4096 + 128) * 4;              // 67,072 B

    cudaFuncSetAttribute(pre_kernel,  cudaFuncAttributeMaxDynamicSharedMemorySize, SMEM_PRE);
    cudaFuncSetAttribute(edge_kernel, cudaFuncAttributeMaxDynamicSharedMemorySize, SMEM_EDGE);
    cudaFuncSetAttribute(upd_kernel,  cudaFuncAttributeMaxDynamicSharedMemorySize, SMEM_UPD);

    dim3 gpre((N + 127) / 128, 2);
    dim3 gupd((N + 127) / 128, 2);
    wfrag_kernel<<<15, 256>>>(msg_w1, msg_w2, mpos_w1, mpos_w2,
                              upd_w1, upd_w2, upe_w1, upe_w2);
    pre_kernel<<<gpre, 256, SMEM_PRE>>>(x, pe, msg_b1, mpos_b1, N);
    edge_kernel<<<(E + 127) / 128, 256, SMEM_EDGE>>>(pos, ei, msg_w1, msg_b2,
                                                     mpos_w1, mpos_b2, E);
    upd_kernel<<<gupd, 256, SMEM_UPD>>>(x, pe, upd_b1, upd_b2, upe_b1, upe_b2,
                                        (float*)d_out, N);
}

// round 17
// speedup vs baseline: 1.0019x; 1.0019x over previous
#include <cuda_runtime.h>
#include <cstdint>

#define NV_MAX 50000
#define HDIM 64

// -------- scratch (no allocs allowed) --------
__device__ float g_A[NV_MAX * HDIM];
__device__ float g_B[NV_MAX * HDIM];
__device__ float g_P[NV_MAX * HDIM];
__device__ float g_Q[NV_MAX * HDIM];
__device__ float g_aggr[NV_MAX * HDIM];
__device__ float g_aggrp[NV_MAX * HDIM];
// precomputed tf32 W fragments (hi[4096] ++ lo[4096] per 64x64 set)
__device__ float g_fragM[8192];            // msg_w2
__device__ float g_fragP[8192];            // mpos_w2
__device__ float g_fragUpd[4 * 8192];      // upd_w1 ch0..2, upd_w2
__device__ float g_fragUpe[3 * 8192];      // upe_w1 ch0..1, upe_w2
__device__ float g_fragPreM[4 * 8192];     // msg_w1 blocks (nh,kc)
__device__ float g_fragPreP[2 * 8192];     // mpos_w1 blocks nh=0,1

typedef unsigned long long ull_t;

__device__ __forceinline__ float tanh_f(float x) {
    float y; asm("tanh.approx.f32 %0, %1;" : "=f"(y) : "f"(x)); return y;
}
__device__ __forceinline__ float silu_f(float x) {
    return 0.5f * x * (1.0f + tanh_f(0.5f * x));   // single MUFU
}
__device__ __forceinline__ uint32_t f2tf32(float x) {
    uint32_t r; asm("cvt.rna.tf32.f32 %0, %1;" : "=r"(r) : "f"(x)); return r;
}
__device__ __forceinline__ void mma_tf32(float c[4],
    uint32_t a0, uint32_t a1, uint32_t a2, uint32_t a3, uint32_t b0, uint32_t b1)
{
    asm volatile(
        "mma.sync.aligned.m16n8k8.row.col.f32.tf32.tf32.f32 "
        "{%0,%1,%2,%3}, {%4,%5,%6,%7}, {%8,%9}, {%0,%1,%2,%3};"
        : "+f"(c[0]), "+f"(c[1]), "+f"(c[2]), "+f"(c[3])
        : "r"(a0), "r"(a1), "r"(a2), "r"(a3), "r"(b0), "r"(b1));
}

// coalesced copy of one 8192-float frag set (hi+lo) into smem
__device__ __forceinline__ void copy_frag(const float* __restrict__ src,
                                          float* __restrict__ dst, int tid)
{
    const float4* s4 = (const float4*)src;
    float4* d4 = (float4*)dst;
    #pragma unroll
    for (int i = 0; i < 8; i++) d4[tid + 256 * i] = s4[tid + 256 * i];
}

// ============================================================
// Kernel 0: W-fragment precompute, one CTA per 64x64 set (15 CTAs)
// ============================================================
__device__ __forceinline__ void build_one(
    const float* __restrict__ src, float* __restrict__ dst, int tid)
{
    for (int idx = tid; idx < 2048; idx += 256) {
        int kt = idx >> 8;
        int nt = (idx >> 5) & 7;
        int ln = idx & 31;
        int g = ln >> 2, t = ln & 3;
        int r = 8 * kt + t, c = 8 * nt + g;
        float w0 = src[r * 64 + c];
        float w1 = src[(r + 4) * 64 + c];
        uint32_t h0 = f2tf32(w0), h1 = f2tf32(w1);
        dst[2 * idx]            = __uint_as_float(h0);
        dst[2 * idx + 1]        = __uint_as_float(h1);
        dst[4096 + 2 * idx]     = __uint_as_float(f2tf32(w0 - __uint_as_float(h0)));
        dst[4096 + 2 * idx + 1] = __uint_as_float(f2tf32(w1 - __uint_as_float(h1)));
    }
}

__global__ void wfrag_kernel(
    const float* __restrict__ msg_w1,  const float* __restrict__ msg_w2,
    const float* __restrict__ mpos_w1, const float* __restrict__ mpos_w2,
    const float* __restrict__ upd_w1,  const float* __restrict__ upd_w2,
    const float* __restrict__ upe_w1,  const float* __restrict__ upe_w2)
{
    int tid = threadIdx.x;
    int b = blockIdx.x;
    if (b == 0)       build_one(msg_w2,  g_fragM, tid);
    else if (b == 1)  build_one(mpos_w2, g_fragP, tid);
    else if (b <= 4)  build_one(upd_w1 + (b - 2) * 4096, g_fragUpd + (b - 2) * 8192, tid);
    else if (b == 5)  build_one(upd_w2, g_fragUpd + 3 * 8192, tid);
    else if (b <= 7)  build_one(upe_w1 + (b - 6) * 4096, g_fragUpe + (b - 6) * 8192, tid);
    else if (b == 8)  build_one(upe_w2, g_fragUpe + 2 * 8192, tid);
    else if (b <= 12) {
        int s = b - 9;                 // s = nh*2 + kc
        int nh = s >> 1, kc = s & 1;
        build_one(msg_w1 + (nh * 128 + kc * 64) * 64, g_fragPreM + s * 8192, tid);
    } else {
        int nh = b - 13;
        build_one(mpos_w1 + nh * 64 * 64, g_fragPreP + nh * 8192, tid);
    }
}

// ============================================================
// Kernel 1 (fused, tf32 mma): blockIdx.y==0 -> A,B (+zero aggr); ==1 -> P,Q
// (unchanged R15 champion)
// ============================================================
__global__ void __launch_bounds__(256, 3) pre_kernel(
    const float* __restrict__ x, const float* __restrict__ pe,
    const float* __restrict__ msg_b1, const float* __restrict__ mpos_b1,
    int N)
{
    extern __shared__ float sm[];
    float* sh_inT = sm;                    // [64][132]
    float* sh_Whi = sh_inT + 64 * 132;     // 4096
    float* sh_Wlo = sh_Whi + 4096;         // 4096
    float* sh_b   = sh_Wlo + 4096;         // [128]

    bool is_pos = (blockIdx.y != 0);
    const float* fragbase = is_pos ? g_fragPreP : g_fragPreM;
    int nkc = is_pos ? 1 : 2;

    int tid = threadIdx.x;
    int nb = blockIdx.x * 128;
    if (tid < 128) sh_b[tid] = (tid < 64) ? (is_pos ? mpos_b1[tid] : msg_b1[tid]) : 0.0f;

    if (!is_pos) {
        for (int idx = tid; idx < 4096; idx += 256) {
            int n = idx & 127, s = (idx >> 7) & 15, which = idx >> 11;
            int gn = nb + n;
            if (gn < N) {
                float4* dst = (float4*)((which ? g_aggrp : g_aggr) + (size_t)gn * 64) + s;
                *dst = make_float4(0.f, 0.f, 0.f, 0.f);
            }
        }
    }

    int w = tid >> 5, lane = tid & 31;
    int gid = lane >> 2, tig = lane & 3;
    int m0 = w * 16;

    #pragma unroll 1
    for (int nh = 0; nh < 2; nh++) {
        float acc[8][4];
        #pragma unroll
        for (int nt = 0; nt < 8; nt++) {
            acc[nt][0] = 0.f; acc[nt][1] = 0.f; acc[nt][2] = 0.f; acc[nt][3] = 0.f;
        }

        #pragma unroll 1
        for (int kc = 0; kc < nkc; kc++) {
            __syncthreads();
            copy_frag(fragbase + (nh * nkc + kc) * 8192, sh_Whi, tid);
            const float* src = is_pos ? pe : ((kc == 0) ? x : pe);
            for (int idx = tid; idx < 16 * 128; idx += 256) {
                int n = idx & 127, k4 = idx >> 7;
                int gn = nb + n;
                float4 v = make_float4(0.f, 0.f, 0.f, 0.f);
                if (gn < N) v = *(const float4*)(src + (size_t)gn * 64 + 4 * k4);
                sh_inT[(4 * k4 + 0) * 132 + n] = v.x;
                sh_inT[(4 * k4 + 1) * 132 + n] = v.y;
                sh_inT[(4 * k4 + 2) * 132 + n] = v.z;
                sh_inT[(4 * k4 + 3) * 132 + n] = v.w;
            }
            __syncthreads();
            #pragma unroll 2
            for (int kt = 0; kt < 8; kt++) {
                const float* tk = sh_inT + (8 * kt + tig) * 132 + m0 + gid;
                float a0f = tk[0],       a1f = tk[8];
                float a2f = tk[4 * 132], a3f = tk[4 * 132 + 8];
                uint32_t ah0 = f2tf32(a0f), ah1 = f2tf32(a1f);
                uint32_t ah2 = f2tf32(a2f), ah3 = f2tf32(a3f);
                uint32_t al0 = f2tf32(a0f - __uint_as_float(ah0));
                uint32_t al1 = f2tf32(a1f - __uint_as_float(ah1));
                uint32_t al2 = f2tf32(a2f - __uint_as_float(ah2));
                uint32_t al3 = f2tf32(a3f - __uint_as_float(ah3));
                #pragma unroll
                for (int nt = 0; nt < 8; nt++) {
                    int fo = ((kt * 8 + nt) * 32 + lane) * 2;
                    float2 bh = *(const float2*)(sh_Whi + fo);
                    float2 bl = *(const float2*)(sh_Wlo + fo);
                    uint32_t bh0 = __float_as_uint(bh.x), bh1 = __float_as_uint(bh.y);
                    uint32_t bl0 = __float_as_uint(bl.x), bl1 = __float_as_uint(bl.y);
                    mma_tf32(acc[nt], ah0, ah1, ah2, ah3, bh0, bh1);
                    mma_tf32(acc[nt], ah0, ah1, ah2, ah3, bl0, bl1);
                    mma_tf32(acc[nt], al0, al1, al2, al3, bh0, bh1);
                }
            }
        }

        float* dst = is_pos ? (nh ? g_Q : g_P) : (nh ? g_B : g_A);
        const float* bb = sh_b + nh * 64;
        int g0 = nb + m0 + gid, g1 = g0 + 8;
        #pragma unroll
        for (int nt = 0; nt < 8; nt++) {
            int c = 8 * nt + 2 * tig;
            float b0 = bb[c], b1 = bb[c + 1];
            if (g0 < N)
                *(float2*)(dst + (size_t)g0 * 64 + c) =
                    make_float2(acc[nt][0] + b0, acc[nt][1] + b1);
            if (g1 < N)
                *(float2*)(dst + (size_t)g1 * 64 + c) =
                    make_float2(acc[nt][2] + b0, acc[nt][3] + b1);
        }
    }
}

// ============================================================
// Kernel 2: edge kernel — tf32 mma 3xTF32, 2 m-tiles x 4 nt-tiles per warp
//   (B fragments reused across 2 m-tiles: 24 smem wf per kt vs 36)
// ============================================================
template <bool IS_TANH>
__device__ __forceinline__ void edge_mma_path(
    const float* __restrict__ sh_t, const float* __restrict__ sh_Whi,
    const float* __restrict__ sh_Wlo, const float* __restrict__ bias,
    const int* __restrict__ rec, float* __restrict__ aggr,
    int w, int lane, int eb, int E)
{
    int gid = lane >> 2, tig = lane & 3;
    int mb  = (w & 3) * 32;          // edges [mb, mb+16), [mb+16, mb+32)
    int ntb = (w >> 2) * 4;          // nt tiles [ntb, ntb+4)

    float acc[8][4];                 // acc[mi*4 + ntl]
    #pragma unroll
    for (int i = 0; i < 8; i++) {
        acc[i][0] = 0.f; acc[i][1] = 0.f; acc[i][2] = 0.f; acc[i][3] = 0.f;
    }

    #pragma unroll 2
    for (int kt = 0; kt < 8; kt++) {
        uint32_t ah[2][4], al[2][4];
        #pragma unroll
        for (int mi = 0; mi < 2; mi++) {
            const float* tk = sh_t + (8 * kt + tig) * 132 + mb + 16 * mi + gid;
            float a0f = tk[0],       a1f = tk[8];
            float a2f = tk[4 * 132], a3f = tk[4 * 132 + 8];
            ah[mi][0] = f2tf32(a0f); ah[mi][1] = f2tf32(a1f);
            ah[mi][2] = f2tf32(a2f); ah[mi][3] = f2tf32(a3f);
            al[mi][0] = f2tf32(a0f - __uint_as_float(ah[mi][0]));
            al[mi][1] = f2tf32(a1f - __uint_as_float(ah[mi][1]));
            al[mi][2] = f2tf32(a2f - __uint_as_float(ah[mi][2]));
            al[mi][3] = f2tf32(a3f - __uint_as_float(ah[mi][3]));
        }
        #pragma unroll
        for (int ntl = 0; ntl < 4; ntl++) {
            int fo = ((kt * 8 + ntb + ntl) * 32 + lane) * 2;
            float2 bh = *(const float2*)(sh_Whi + fo);
            float2 bl = *(const float2*)(sh_Wlo + fo);
            uint32_t bh0 = __float_as_uint(bh.x), bh1 = __float_as_uint(bh.y);
            uint32_t bl0 = __float_as_uint(bl.x), bl1 = __float_as_uint(bl.y);
            #pragma unroll
            for (int mi = 0; mi < 2; mi++) {
                float* a = acc[mi * 4 + ntl];
                mma_tf32(a, ah[mi][0], ah[mi][1], ah[mi][2], ah[mi][3], bh0, bh1);
                mma_tf32(a, ah[mi][0], ah[mi][1], ah[mi][2], ah[mi][3], bl0, bl1);
                mma_tf32(a, al[mi][0], al[mi][1], al[mi][2], al[mi][3], bh0, bh1);
            }
        }
    }

    #pragma unroll
    for (int mi = 0; mi < 2; mi++) {
        int el0 = mb + 16 * mi + gid, el1 = el0 + 8;
        bool v0 = (eb + el0 < E), v1 = (eb + el1 < E);
        int rc0 = rec[el0], rc1 = rec[el1];
        #pragma unroll
        for (int ntl = 0; ntl < 4; ntl++) {
            int c = 8 * (ntb + ntl) + 2 * tig;
            float b0 = bias[c], b1 = bias[c + 1];
            const float* a = acc[mi * 4 + ntl];
            if (v0) {
                float m0 = a[0] + b0, m1 = a[1] + b1;
                if (IS_TANH) { m0 = tanh_f(m0); m1 = tanh_f(m1); }
                else         { m0 = silu_f(m0); m1 = silu_f(m1); }
                float* dst = aggr + (size_t)rc0 * 64 + c;
                asm volatile("red.global.add.v2.f32 [%0], {%1,%2};"
                             :: "l"(dst), "f"(m0), "f"(m1) : "memory");
            }
            if (v1) {
                float m0 = a[2] + b0, m1 = a[3] + b1;
                if (IS_TANH) { m0 = tanh_f(m0); m1 = tanh_f(m1); }
                else         { m0 = silu_f(m0); m1 = silu_f(m1); }
                float* dst = aggr + (size_t)rc1 * 64 + c;
                asm volatile("red.global.add.v2.f32 [%0], {%1,%2};"
                             :: "l"(dst), "f"(m0), "f"(m1) : "memory");
            }
        }
    }
}

__global__ void __launch_bounds__(256, 3) edge_kernel(
    const float* __restrict__ pos,
    const int* __restrict__ ei,          // int32 (JAX demotes int64)
    const float* __restrict__ msg_w1,
    const float* __restrict__ msg_b2,
    const float* __restrict__ mpos_w1,
    const float* __restrict__ mpos_b2,
    int E)
{
    extern __shared__ float sm[];
    float* sh_t   = sm;                    // [64][132]
    float* sh_Whi = sh_t + 64 * 132;       // 4096 (hi; lo contiguous)
    float* sh_Wlo = sh_Whi + 4096;         // 4096
    float* sh_we  = sh_Wlo + 4096;         // [64]
    float* sh_ve  = sh_we + 64;
    float* sh_bm  = sh_ve + 64;
    float* sh_bp  = sh_bm + 64;
    int*   sh_rec = (int*)(sh_bp + 64);    // [128]

    int tid = threadIdx.x;
    copy_frag(g_fragM, sh_Whi, tid);
    if (tid < 64) {
        sh_we[tid] = msg_w1[256 * 64 + tid];
        sh_ve[tid] = mpos_w1[128 * 64 + tid];
        sh_bm[tid] = msg_b2[tid];
        sh_bp[tid] = mpos_b2[tid];
    }

    int eb = blockIdx.x * 128;
    int e  = tid & 127;
    int half = tid >> 7;
    int eg = eb + e;
    bool valid = eg < E;
    int snd = 0, rcv = 0;
    if (valid) { snd = ei[eg]; rcv = ei[E + eg]; }
    if (half == 0) sh_rec[e] = rcv;
    float dist = 0.0f;
    if (valid) {
        float dx = pos[snd * 3 + 0] - pos[rcv * 3 + 0];
        float dy = pos[snd * 3 + 1] - pos[rcv * 3 + 1];
        float dz = pos[snd * 3 + 2] - pos[rcv * 3 + 2];
        dist = sqrtf(dx * dx + dy * dy + dz * dz);
    }
    __syncthreads();

    int c0h = half * 32;
    int w = tid >> 5, lane = tid & 31;

    // ---- phase A: silu(A[snd]+B[rcv]+dist*we) -> sh_t, then msg GEMM ----
    {
        const float4* A4 = (const float4*)(g_A + (size_t)snd * 64 + c0h);
        const float4* B4 = (const float4*)(g_B + (size_t)rcv * 64 + c0h);
        const float4* W4 = (const float4*)(sh_we + c0h);
        #pragma unroll
        for (int j = 0; j < 8; j++) {
            float4 a = A4[j], b = B4[j], wv = W4[j];
            float* dst = sh_t + (c0h + 4 * j) * 132 + e;
            dst[0]   = silu_f(a.x + b.x + dist * wv.x);
            dst[132] = silu_f(a.y + b.y + dist * wv.y);
            dst[264] = silu_f(a.z + b.z + dist * wv.z);
            dst[396] = silu_f(a.w + b.w + dist * wv.w);
        }
    }
    __syncthreads();
    edge_mma_path<false>(sh_t, sh_Whi, sh_Wlo, sh_bm, sh_rec, g_aggr, w, lane, eb, E);
    __syncthreads();

    // ---- phase B: copy pos frags; tanh tile; pos GEMM ----
    copy_frag(g_fragP, sh_Whi, tid);
    {
        const float4* P4 = (const float4*)(g_P + (size_t)snd * 64 + c0h);
        const float4* Q4 = (const float4*)(g_Q + (size_t)rcv * 64 + c0h);
        const float4* V4 = (const float4*)(sh_ve + c0h);
        #pragma unroll
        for (int j = 0; j < 8; j++) {
            float4 p = P4[j], q = Q4[j], v = V4[j];
            float* dst = sh_t + (c0h + 4 * j) * 132 + e;
            dst[0]   = tanh_f(p.x + q.x + dist * v.x);
            dst[132] = tanh_f(p.y + q.y + dist * v.y);
            dst[264] = tanh_f(p.z + q.z + dist * v.z);
            dst[396] = tanh_f(p.w + q.w + dist * v.w);
        }
    }
    __syncthreads();
    edge_mma_path<true>(sh_t, sh_Whi, sh_Wlo, sh_bp, sh_rec, g_aggrp, w, lane, eb, E);
}

// ============================================================
// Kernel 3 (fused): tf32 mma with precomputed frags
// (unchanged R14/R15 champion)
// ============================================================
__global__ void __launch_bounds__(256, 3) upd_kernel(
    const float* __restrict__ x, const float* __restrict__ pe,
    const float* __restrict__ upd_b1, const float* __restrict__ upd_b2,
    const float* __restrict__ upe_b1, const float* __restrict__ upe_b2,
    float* __restrict__ out, int N)
{
    extern __shared__ float sm[];
    float* sh_inT = sm;                    // [64][132] (chunk; reused as hT)
    float* sh_Whi = sh_inT + 64 * 132;     // 4096
    float* sh_Wlo = sh_Whi + 4096;         // 4096
    float* sh_b1  = sh_Wlo + 4096;         // [64]
    float* sh_b2  = sh_b1 + 64;            // [64]

    bool is_pe = (blockIdx.y != 0);
    const float* fragbase = is_pe ? g_fragUpe : g_fragUpd;
    int nchunks = is_pe ? 2 : 3;

    int tid = threadIdx.x;
    int nb = blockIdx.x * 128;
    if (tid < 64) {
        sh_b1[tid] = is_pe ? upe_b1[tid] : upd_b1[tid];
        sh_b2[tid] = is_pe ? upe_b2[tid] : upd_b2[tid];
    }

    int w = tid >> 5, lane = tid & 31;
    int gid = lane >> 2, tig = lane & 3;
    int m0 = w * 16;

    float acc[8][4];
    #pragma unroll
    for (int nt = 0; nt < 8; nt++) {
        acc[nt][0] = 0.f; acc[nt][1] = 0.f; acc[nt][2] = 0.f; acc[nt][3] = 0.f;
    }

    #pragma unroll 1
    for (int ch = 0; ch < nchunks; ch++) {
        __syncthreads();
        copy_frag(fragbase + ch * 8192, sh_Whi, tid);
        const float* src = is_pe ? ((ch == 0) ? pe : g_aggrp)
                                 : ((ch == 0) ? x : (ch == 1) ? pe : g_aggr);
        for (int idx = tid; idx < 16 * 128; idx += 256) {
            int n = idx & 127, k4 = idx >> 7;
            int gn = nb + n;
            float4 v = make_float4(0.f, 0.f, 0.f, 0.f);
            if (gn < N) v = *(const float4*)(src + (size_t)gn * 64 + 4 * k4);
            sh_inT[(4 * k4 + 0) * 132 + n] = v.x;
            sh_inT[(4 * k4 + 1) * 132 + n] = v.y;
            sh_inT[(4 * k4 + 2) * 132 + n] = v.z;
            sh_inT[(4 * k4 + 3) * 132 + n] = v.w;
        }
        __syncthreads();
        #pragma unroll 2
        for (int kt = 0; kt < 8; kt++) {
            const float* tk = sh_inT + (8 * kt + tig) * 132 + m0 + gid;
            float a0f = tk[0],       a1f = tk[8];
            float a2f = tk[4 * 132], a3f = tk[4 * 132 + 8];
            uint32_t ah0 = f2tf32(a0f), ah1 = f2tf32(a1f);
            uint32_t ah2 = f2tf32(a2f), ah3 = f2tf32(a3f);
            uint32_t al0 = f2tf32(a0f - __uint_as_float(ah0));
            uint32_t al1 = f2tf32(a1f - __uint_as_float(ah1));
            uint32_t al2 = f2tf32(a2f - __uint_as_float(ah2));
            uint32_t al3 = f2tf32(a3f - __uint_as_float(ah3));
            #pragma unroll
            for (int nt = 0; nt < 8; nt++) {
                int fo = ((kt * 8 + nt) * 32 + lane) * 2;
                float2 bh = *(const float2*)(sh_Whi + fo);
                float2 bl = *(const float2*)(sh_Wlo + fo);
                uint32_t bh0 = __float_as_uint(bh.x), bh1 = __float_as_uint(bh.y);
                uint32_t bl0 = __float_as_uint(bl.x), bl1 = __float_as_uint(bl.y);
                mma_tf32(acc[nt], ah0, ah1, ah2, ah3, bh0, bh1);
                mma_tf32(acc[nt], ah0, ah1, ah2, ah3, bl0, bl1);
                mma_tf32(acc[nt], al0, al1, al2, al3, bh0, bh1);
            }
        }
    }

    __syncthreads();
    #pragma unroll
    for (int nt = 0; nt < 8; nt++) {
        int c = 8 * nt + 2 * tig;
        float b0 = sh_b1[c], b1 = sh_b1[c + 1];
        float h00 = acc[nt][0] + b0, h01 = acc[nt][1] + b1;
        float h10 = acc[nt][2] + b0, h11 = acc[nt][3] + b1;
        if (is_pe) { h00 = tanh_f(h00); h01 = tanh_f(h01); h10 = tanh_f(h10); h11 = tanh_f(h11); }
        else       { h00 = silu_f(h00); h01 = silu_f(h01); h10 = silu_f(h10); h11 = silu_f(h11); }
        sh_inT[c * 132 + m0 + gid]           = h00;
        sh_inT[(c + 1) * 132 + m0 + gid]     = h01;
        sh_inT[c * 132 + m0 + gid + 8]       = h10;
        sh_inT[(c + 1) * 132 + m0 + gid + 8] = h11;
    }
    copy_frag(fragbase + (is_pe ? 2 : 3) * 8192, sh_Whi, tid);
    __syncthreads();

    float a2[8][4];
    #pragma unroll
    for (int nt = 0; nt < 8; nt++) {
        a2[nt][0] = 0.f; a2[nt][1] = 0.f; a2[nt][2] = 0.f; a2[nt][3] = 0.f;
    }
    #pragma unroll 2
    for (int kt = 0; kt < 8; kt++) {
        const float* tk = sh_inT + (8 * kt + tig) * 132 + m0 + gid;
        float a0f = tk[0],       a1f = tk[8];
        float a2f = tk[4 * 132], a3f = tk[4 * 132 + 8];
        uint32_t ah0 = f2tf32(a0f), ah1 = f2tf32(a1f);
        uint32_t ah2 = f2tf32(a2f), ah3 = f2tf32(a3f);
        uint32_t al0 = f2tf32(a0f - __uint_as_float(ah0));
        uint32_t al1 = f2tf32(a1f - __uint_as_float(ah1));
        uint32_t al2 = f2tf32(a2f - __uint_as_float(ah2));
        uint32_t al3 = f2tf32(a3f - __uint_as_float(ah3));
        #pragma unroll
        for (int nt = 0; nt < 8; nt++) {
            int fo = ((kt * 8 + nt) * 32 + lane) * 2;
            float2 bh = *(const float2*)(sh_Whi + fo);
            float2 bl = *(const float2*)(sh_Wlo + fo);
            uint32_t bh0 = __float_as_uint(bh.x), bh1 = __float_as_uint(bh.y);
            uint32_t bl0 = __float_as_uint(bl.x), bl1 = __float_as_uint(bl.y);
            mma_tf32(a2[nt], ah0, ah1, ah2, ah3, bh0, bh1);
            mma_tf32(a2[nt], ah0, ah1, ah2, ah3, bl0, bl1);
            mma_tf32(a2[nt], al0, al1, al2, al3, bh0, bh1);
        }
    }

    float* obase = out + (is_pe ? (size_t)N * 64 : 0);
    int g0 = nb + m0 + gid, g1 = g0 + 8;
    #pragma unroll
    for (int nt = 0; nt < 8; nt++) {
        int c = 8 * nt + 2 * tig;
        float b0 = sh_b2[c], b1 = sh_b2[c + 1];
        if (g0 < N) {
            float o0 = a2[nt][0] + b0, o1 = a2[nt][1] + b1;
            if (is_pe) { o0 = tanh_f(o0); o1 = tanh_f(o1); }
            *(float2*)(obase + (size_t)g0 * 64 + c) = make_float2(o0, o1);
        }
        if (g1 < N) {
            float o0 = a2[nt][2] + b0, o1 = a2[nt][3] + b1;
            if (is_pe) { o0 = tanh_f(o0); o1 = tanh_f(o1); }
            *(float2*)(obase + (size_t)g1 * 64 + c) = make_float2(o0, o1);
        }
    }
}

// ============================================================
// Host launch
// ============================================================
extern "C" void kernel_launch(void* const* d_in, const int* in_sizes, int n_in,
                              void* d_out, int out_size)
{
    const float* x       = (const float*)d_in[0];
    const float* pos     = (const float*)d_in[1];
    const float* pe      = (const float*)d_in[2];
    const int*   ei      = (const int*)d_in[3];
    const float* msg_w1  = (const float*)d_in[4];
    const float* msg_b1  = (const float*)d_in[5];
    const float* msg_w2  = (const float*)d_in[6];
    const float* msg_b2  = (const float*)d_in[7];
    const float* mpos_w1 = (const float*)d_in[8];
    const float* mpos_b1 = (const float*)d_in[9];
    const float* mpos_w2 = (const float*)d_in[10];
    const float* mpos_b2 = (const float*)d_in[11];
    const float* upd_w1  = (const float*)d_in[12];
    const float* upd_b1  = (const float*)d_in[13];
    const float* upd_w2  = (const float*)d_in[14];
    const float* upd_b2  = (const float*)d_in[15];
    const float* upe_w1  = (const float*)d_in[16];
    const float* upe_b1  = (const float*)d_in[17];
    const float* upe_w2  = (const float*)d_in[18];
    const float* upe_b2  = (const float*)d_in[19];

    int N = in_sizes[0] / 64;
    int E = in_sizes[3] / 2;

    const int SMEM_PRE  = (64 * 132 + 4096 + 4096 + 128) * 4;              // 67,072 B
    const int SMEM_EDGE = (64 * 132 + 4096 + 4096 + 256) * 4 + 512;        // 68,096 B
    const int SMEM_UPD  = (64 * 132 + 4096 + 4096 + 128) * 4;              // 67,072 B

    cudaFuncSetAttribute(pre_kernel,  cudaFuncAttributeMaxDynamicSharedMemorySize, SMEM_PRE);
    cudaFuncSetAttribute(edge_kernel, cudaFuncAttributeMaxDynamicSharedMemorySize, SMEM_EDGE);
    cudaFuncSetAttribute(upd_kernel,  cudaFuncAttributeMaxDynamicSharedMemorySize, SMEM_UPD);

    dim3 gpre((N + 127) / 128, 2);
    dim3 gupd((N + 127) / 128, 2);
    wfrag_kernel<<<15, 256>>>(msg_w1, msg_w2, mpos_w1, mpos_w2,
                              upd_w1, upd_w2, upe_w1, upe_w2);
    pre_kernel<<<gpre, 256, SMEM_PRE>>>(x, pe, msg_b1, mpos_b1, N);
    edge_kernel<<<(E + 127) / 128, 256, SMEM_EDGE>>>(pos, ei, msg_w1, msg_b2,
                                                     mpos_w1, mpos_b2, E);
    upd_kernel<<<gupd, 256, SMEM_UPD>>>(x, pe, upd_b1, upd_b2, upe_b1, upe_b2,
                                        (float*)d_out, N);
}